// round 11
// baseline (speedup 1.0000x reference)
#include <cuda_runtime.h>

// GlobalContextAttention — register-resident single-read kernel.
// x (J, F, C=128) fp32, batch_index (F,) int32 SORTED, weight (C,C) fp32 -> out (J, B, C).
//
// R7-R10 lesson: any second architectural read of the slice (L2 or smem) costs
// capacity thrash or latency. Fix: hold the slice in REGISTERS. 1024-thread CTA
// per (j,b); thread (warp w, lane l) holds frames f = start+w+k*32 (k<10) as
// float4 of channels l*4.. in registers during pass1; pass2 computes gates from
// those registers -> x is read once, no re-read anywhere. Overflow frames
// (segments > ~320) take a rare L2-hot fallback. 10 back-to-back loads/warp
// x 32 warps = 40KB in flight/SM -> BW-bound, not latency-bound.

static constexpr int C_DIM   = 128;
static constexpr int THREADS = 1024;
static constexpr int WARPS   = 32;
static constexpr int KMAX    = 10;      // frames/thread held in registers
static constexpr int MAX_SEG = 4096;

__device__ int g_seg[MAX_SEG + 1];

__global__ void seg_bounds_kernel(const int* __restrict__ idx, int Fn, int Bn)
{
    const int t = blockIdx.x * blockDim.x + threadIdx.x;
    if (t > Bn) return;
    int lo = 0, hi = Fn;
    while (lo < hi) {
        int m = (lo + hi) >> 1;
        if (idx[m] < t) lo = m + 1; else hi = m;
    }
    g_seg[t] = lo;
}

__global__ __launch_bounds__(THREADS, 1)
void gca_fused_kernel(const float* __restrict__ x,
                      const float* __restrict__ W,
                      float*       __restrict__ out,
                      int Jn, int Fn, int Bn)
{
    __shared__ float s_red[WARPS * C_DIM];   // 16 KB
    __shared__ float s_vec[C_DIM];           // mean, then gc

    const int tid  = threadIdx.x;
    const int warp = tid >> 5;
    const int lane = tid & 31;
    const int b    = blockIdx.x;
    const int j    = blockIdx.y;

    const int start = g_seg[b];
    const int end   = g_seg[b + 1];
    const int cnt   = end - start;
    const float inv_cnt = 1.0f / (float)(cnt > 0 ? cnt : 1);
    const int ch = lane * 4;
    const float* xj = x + (size_t)j * Fn * C_DIM;
    const int base = start + warp;           // this warp's frame ladder: base + k*32

    // ---------------- pass 1: load slice into registers + per-channel sum ----
    float4 v[KMAX];
    float4 acc = make_float4(0.f, 0.f, 0.f, 0.f);
#pragma unroll
    for (int k = 0; k < KMAX; k++) {
        const int f = base + k * WARPS;
        if (f < end) {
            v[k] = *(const float4*)(xj + (size_t)f * C_DIM + ch);
            acc.x += v[k].x; acc.y += v[k].y; acc.z += v[k].z; acc.w += v[k].w;
        }
    }
    // overflow frames (rare: segments longer than KMAX*32)
    for (int f = base + KMAX * WARPS; f < end; f += WARPS) {
        const float4 a = *(const float4*)(xj + (size_t)f * C_DIM + ch);
        acc.x += a.x; acc.y += a.y; acc.z += a.z; acc.w += a.w;
    }
    *(float4*)&s_red[warp * C_DIM + ch] = acc;
    __syncthreads();
    if (tid < C_DIM) {
        float s = 0.f;
#pragma unroll
        for (int w = 0; w < WARPS; w++) s += s_red[w * C_DIM + tid];
        s_vec[tid] = s * inv_cnt;            // mean[j,b,:]
    }
    __syncthreads();

    // ---------------- GEMV: gc = tanh(mean @ W), 8-way k split ----------------
    {
        const int t_out = tid & (C_DIM - 1);
        const int q     = tid >> 7;          // 0..7, k in [q*16, q*16+16)
        const float* wp = W + (size_t)(q * 16) * C_DIM + t_out;
        float p = 0.f;
#pragma unroll
        for (int k = 0; k < 16; k++)
            p += s_vec[q * 16 + k] * wp[(size_t)k * C_DIM];
        __syncthreads();                     // mean reads done before overwrite
        s_red[q * C_DIM + t_out] = p;
    }
    __syncthreads();
    if (tid < C_DIM) {
        float g = 0.f;
#pragma unroll
        for (int q = 0; q < 8; q++) g += s_red[q * C_DIM + tid];
        s_vec[tid] = tanhf(g);               // gc[j,b,:]
    }
    __syncthreads();

    // ---------------- pass 2: gates from registers (no re-read) ----------------
    const float4 gc4 = *(const float4*)&s_vec[ch];
    float4 oacc = make_float4(0.f, 0.f, 0.f, 0.f);
#pragma unroll
    for (int kb = 0; kb < KMAX; kb += 5) {
        float d[5];
#pragma unroll
        for (int u = 0; u < 5; u++) {
            const int k = kb + u;
            if (k < KMAX && base + k * WARPS < end)
                d[u] = v[k].x*gc4.x + v[k].y*gc4.y + v[k].z*gc4.z + v[k].w*gc4.w;
            else
                d[u] = 0.f;
        }
#pragma unroll
        for (int s = 16; s > 0; s >>= 1) {
#pragma unroll
            for (int u = 0; u < 5; u++)
                d[u] += __shfl_xor_sync(0xffffffffu, d[u], s);
        }
#pragma unroll
        for (int u = 0; u < 5; u++) {
            const int k = kb + u;
            if (k < KMAX && base + k * WARPS < end) {
                const float g = 1.f / (1.f + __expf(-d[u]));
                oacc.x += g * v[k].x; oacc.y += g * v[k].y;
                oacc.z += g * v[k].z; oacc.w += g * v[k].w;
            }
        }
    }
    // overflow frames: re-read from global (L2-hot, rare)
    for (int f = base + KMAX * WARPS; f < end; f += WARPS) {
        const float4 a = *(const float4*)(xj + (size_t)f * C_DIM + ch);
        float d = a.x*gc4.x + a.y*gc4.y + a.z*gc4.z + a.w*gc4.w;
#pragma unroll
        for (int s = 16; s > 0; s >>= 1)
            d += __shfl_xor_sync(0xffffffffu, d, s);
        const float g = 1.f / (1.f + __expf(-d));
        oacc.x += g * a.x; oacc.y += g * a.y; oacc.z += g * a.z; oacc.w += g * a.w;
    }

    __syncthreads();                         // s_red free for reuse
    *(float4*)&s_red[warp * C_DIM + ch] = oacc;
    __syncthreads();
    if (tid < C_DIM) {
        float s = 0.f;
#pragma unroll
        for (int w = 0; w < WARPS; w++) s += s_red[w * C_DIM + tid];
        out[((size_t)j * Bn + b) * C_DIM + tid] = s * inv_cnt;
    }
}

extern "C" void kernel_launch(void* const* d_in, const int* in_sizes, int n_in,
                              void* d_out, int out_size)
{
    // Identify inputs by element count: x = largest; weight = C*C; idx = other multi-element.
    int xi = 0;
    for (int i = 1; i < n_in; i++)
        if (in_sizes[i] > in_sizes[xi]) xi = i;
    int wi = -1, ii = -1;
    for (int i = 0; i < n_in; i++) {
        if (i == xi) continue;
        if (in_sizes[i] == C_DIM * C_DIM && wi < 0) { wi = i; continue; }
        if (in_sizes[i] > 1 && ii < 0) ii = i;
    }
    if (wi < 0 || ii < 0) return;

    const float* x   = (const float*)d_in[xi];
    const int*   idx = (const int*)  d_in[ii];
    const float* W   = (const float*)d_in[wi];
    float*       out = (float*)d_out;

    const int Fn = in_sizes[ii];
    const int Jn = in_sizes[xi] / (Fn * C_DIM);
    int Bn = out_size / (Jn * C_DIM);
    if (Bn > MAX_SEG) Bn = MAX_SEG;

    seg_bounds_kernel<<<(Bn + 255) / 256 + 1, 256>>>(idx, Fn, Bn);
    dim3 grid(Bn, Jn);
    gca_fused_kernel<<<grid, THREADS>>>(x, W, out, Jn, Fn, Bn);
}

// round 12
// speedup vs baseline: 1.0354x; 1.0354x over previous
#include <cuda_runtime.h>
#include <cstdint>

// GlobalContextAttention — cp.async full-slice smem staging, single DRAM read.
// x (J, F, C=128) fp32, batch_index (F,) int32 SORTED, weight (C,C) fp32 -> out (J, B, C).
//
// R5-R11 synthesis: serial two-pass tops out ~140us; overlap via L2 thrashes;
// register residency doesn't fit 64 regs. This version stages the ENTIRE
// (j,b) slice (~300 frames = ~150KB, CAP=384) into smem with per-thread
// cp.async.cg (LDGSTS: no register payload -> whole slice in flight at once),
// sums pass1 chunk-by-chunk under the copy (commit_group/wait_group), then
// runs gemv + pass2 entirely from smem. x is read from DRAM exactly once and
// never re-read from L2 -> no capacity coupling; grid = (B, J) independent CTAs.

static constexpr int C_DIM   = 128;
static constexpr int THREADS = 1024;
static constexpr int WARPS   = 32;
static constexpr int CAP     = 384;     // staged frames (192 KB)
static constexpr int MAX_SEG = 4096;
static constexpr int SMEM_BYTES = (CAP * C_DIM + WARPS * C_DIM + C_DIM) * 4; // 213,504 B

__device__ int g_seg[MAX_SEG + 1];

__global__ void seg_bounds_kernel(const int* __restrict__ idx, int Fn, int Bn)
{
    const int t = blockIdx.x * blockDim.x + threadIdx.x;
    if (t > Bn) return;
    int lo = 0, hi = Fn;
    while (lo < hi) {
        int m = (lo + hi) >> 1;
        if (idx[m] < t) lo = m + 1; else hi = m;
    }
    g_seg[t] = lo;
}

__device__ __forceinline__ uint32_t s2u(const void* p) {
    uint32_t a;
    asm("{ .reg .u64 t; cvta.to.shared.u64 t, %1; cvt.u32.u64 %0, t; }" : "=r"(a) : "l"(p));
    return a;
}

__global__ __launch_bounds__(THREADS, 1)
void gca_fused_kernel(const float* __restrict__ x,
                      const float* __restrict__ W,
                      float*       __restrict__ out,
                      int Jn, int Fn, int Bn)
{
    extern __shared__ float dyn[];
    float* buf   = dyn;                        // CAP x 128 staged slice
    float* s_red = dyn + CAP * C_DIM;          // 32 x 128 reduction buffer
    float* s_vec = s_red + WARPS * C_DIM;      // 128: mean, then gc

    const int tid  = threadIdx.x;
    const int warp = tid >> 5;
    const int lane = tid & 31;
    const int b    = blockIdx.x;
    const int j    = blockIdx.y;

    const int start = g_seg[b];
    const int end   = g_seg[b + 1];
    const int cnt   = end - start;
    const int staged = cnt < CAP ? cnt : CAP;
    const float inv_cnt = 1.0f / (float)(cnt > 0 ? cnt : 1);
    const int ch = lane * 4;
    const float* gsrc = x + ((size_t)j * Fn + start) * C_DIM;  // contiguous slice
    const uint32_t sbase = s2u(buf);

    // chunk boundaries in frames (4 chunks; granule = 16B, 32 granules/frame)
    int fch[5];
#pragma unroll
    for (int c = 0; c <= 4; c++) fch[c] = (staged * c) >> 2;

    // ---------------- issue all cp.async chunks (flat byte copy) ----------------
#pragma unroll
    for (int c = 0; c < 4; c++) {
        const int g0 = fch[c] * 32, g1 = fch[c + 1] * 32;
        for (int g = g0 + tid; g < g1; g += THREADS) {
            asm volatile("cp.async.cg.shared.global [%0], [%1], 16;"
                         :: "r"(sbase + (uint32_t)g * 16), "l"(gsrc + (size_t)g * 4)
                         : "memory");
        }
        asm volatile("cp.async.commit_group;" ::: "memory");
    }

    // ---------------- pass 1: sum chunk-by-chunk as copies land ----------------
    float4 acc = make_float4(0.f, 0.f, 0.f, 0.f);
#pragma unroll
    for (int c = 0; c < 4; c++) {
        if (c == 0)      asm volatile("cp.async.wait_group 3;" ::: "memory");
        else if (c == 1) asm volatile("cp.async.wait_group 2;" ::: "memory");
        else if (c == 2) asm volatile("cp.async.wait_group 1;" ::: "memory");
        else             asm volatile("cp.async.wait_group 0;" ::: "memory");
        __syncthreads();
        for (int f = fch[c] + warp; f < fch[c + 1]; f += WARPS) {
            const float4 a = *(const float4*)(buf + f * C_DIM + ch);
            acc.x += a.x; acc.y += a.y; acc.z += a.z; acc.w += a.w;
        }
    }
    // overflow frames (cnt > CAP, rare): direct global
    for (int f = staged + warp; f < cnt; f += WARPS) {
        const float4 a = *(const float4*)(gsrc + (size_t)f * C_DIM + ch);
        acc.x += a.x; acc.y += a.y; acc.z += a.z; acc.w += a.w;
    }
    *(float4*)&s_red[warp * C_DIM + ch] = acc;
    __syncthreads();
    if (tid < C_DIM) {
        float s = 0.f;
#pragma unroll
        for (int w = 0; w < WARPS; w++) s += s_red[w * C_DIM + tid];
        s_vec[tid] = s * inv_cnt;              // mean[j,b,:]
    }
    __syncthreads();

    // ---------------- GEMV: gc = tanh(mean @ W), 8-way k split ----------------
    {
        const int t_out = tid & (C_DIM - 1);
        const int q     = tid >> 7;            // 0..7, k in [q*16, q*16+16)
        const float* wp = W + (size_t)(q * 16) * C_DIM + t_out;
        float p = 0.f;
#pragma unroll
        for (int k = 0; k < 16; k++)
            p += s_vec[q * 16 + k] * wp[(size_t)k * C_DIM];
        __syncthreads();                       // mean reads done before overwrite
        s_red[q * C_DIM + t_out] = p;
    }
    __syncthreads();
    if (tid < C_DIM) {
        float g = 0.f;
#pragma unroll
        for (int q = 0; q < 8; q++) g += s_red[q * C_DIM + tid];
        s_vec[tid] = tanhf(g);                 // gc[j,b,:]
    }
    __syncthreads();

    // ---------------- pass 2: gates from smem (no global re-read) --------------
    const float4 gc4 = *(const float4*)&s_vec[ch];
    float4 oacc = make_float4(0.f, 0.f, 0.f, 0.f);
    int f = warp;
    for (; f + WARPS < staged; f += 2 * WARPS) {
        const float4 a0 = *(const float4*)(buf + f * C_DIM + ch);
        const float4 a1 = *(const float4*)(buf + (f + WARPS) * C_DIM + ch);
        float d0 = a0.x*gc4.x + a0.y*gc4.y + a0.z*gc4.z + a0.w*gc4.w;
        float d1 = a1.x*gc4.x + a1.y*gc4.y + a1.z*gc4.z + a1.w*gc4.w;
#pragma unroll
        for (int s = 16; s > 0; s >>= 1) {
            d0 += __shfl_xor_sync(0xffffffffu, d0, s);
            d1 += __shfl_xor_sync(0xffffffffu, d1, s);
        }
        const float g0 = 1.f / (1.f + __expf(-d0));
        const float g1 = 1.f / (1.f + __expf(-d1));
        oacc.x += g0*a0.x + g1*a1.x; oacc.y += g0*a0.y + g1*a1.y;
        oacc.z += g0*a0.z + g1*a1.z; oacc.w += g0*a0.w + g1*a1.w;
    }
    for (; f < staged; f += WARPS) {
        const float4 a = *(const float4*)(buf + f * C_DIM + ch);
        float d = a.x*gc4.x + a.y*gc4.y + a.z*gc4.z + a.w*gc4.w;
#pragma unroll
        for (int s = 16; s > 0; s >>= 1)
            d += __shfl_xor_sync(0xffffffffu, d, s);
        const float g = 1.f / (1.f + __expf(-d));
        oacc.x += g*a.x; oacc.y += g*a.y; oacc.z += g*a.z; oacc.w += g*a.w;
    }
    // overflow frames: direct global (L2-hot from pass1's read)
    for (int f2 = staged + warp; f2 < cnt; f2 += WARPS) {
        const float4 a = *(const float4*)(gsrc + (size_t)f2 * C_DIM + ch);
        float d = a.x*gc4.x + a.y*gc4.y + a.z*gc4.z + a.w*gc4.w;
#pragma unroll
        for (int s = 16; s > 0; s >>= 1)
            d += __shfl_xor_sync(0xffffffffu, d, s);
        const float g = 1.f / (1.f + __expf(-d));
        oacc.x += g*a.x; oacc.y += g*a.y; oacc.z += g*a.z; oacc.w += g*a.w;
    }

    __syncthreads();                           // s_red free for reuse
    *(float4*)&s_red[warp * C_DIM + ch] = oacc;
    __syncthreads();
    if (tid < C_DIM) {
        float s = 0.f;
#pragma unroll
        for (int w = 0; w < WARPS; w++) s += s_red[w * C_DIM + tid];
        out[((size_t)j * Bn + b) * C_DIM + tid] = s * inv_cnt;
    }
}

extern "C" void kernel_launch(void* const* d_in, const int* in_sizes, int n_in,
                              void* d_out, int out_size)
{
    // Identify inputs by element count: x = largest; weight = C*C; idx = other multi-element.
    int xi = 0;
    for (int i = 1; i < n_in; i++)
        if (in_sizes[i] > in_sizes[xi]) xi = i;
    int wi = -1, ii = -1;
    for (int i = 0; i < n_in; i++) {
        if (i == xi) continue;
        if (in_sizes[i] == C_DIM * C_DIM && wi < 0) { wi = i; continue; }
        if (in_sizes[i] > 1 && ii < 0) ii = i;
    }
    if (wi < 0 || ii < 0) return;

    const float* x   = (const float*)d_in[xi];
    const int*   idx = (const int*)  d_in[ii];
    const float* W   = (const float*)d_in[wi];
    float*       out = (float*)d_out;

    const int Fn = in_sizes[ii];
    const int Jn = in_sizes[xi] / (Fn * C_DIM);
    int Bn = out_size / (Jn * C_DIM);
    if (Bn > MAX_SEG) Bn = MAX_SEG;

    static bool attr_set = false;
    if (!attr_set) {
        cudaFuncSetAttribute(gca_fused_kernel,
                             cudaFuncAttributeMaxDynamicSharedMemorySize, SMEM_BYTES);
        attr_set = true;
    }

    seg_bounds_kernel<<<(Bn + 255) / 256 + 1, 256>>>(idx, Fn, Bn);
    dim3 grid(Bn, Jn);
    gca_fused_kernel<<<grid, THREADS, SMEM_BYTES>>>(x, W, out, Jn, Fn, Bn);
}

// round 13
// speedup vs baseline: 1.0954x; 1.0579x over previous
#include <cuda_runtime.h>

// GlobalContextAttention — R5 structure + free smem staging of the slice head.
// x (J, F, C=128) fp32, batch_index (F,) int32 SORTED, weight (C,C) fp32 -> out (J, B, C).
//
// R5 (139.6us) sits on its serial floor: pass1(DRAM) + pass2(L2). R12's change:
// during pass1, the first STAGE=96 frames are also stored to smem (issue-only
// cost, ordered by the existing mean barrier). Pass2 reads 32% from smem and
// the rest from an L2 set shrunk to ~62MB (4 CTAs/SM x 148 x 204 frames),
// cutting pass2 time and L2 traffic. STAGE = 12*WARPS so the staged loop has
// no mixed predication. Smem 52.5KB/CTA pins occupancy at 4/SM.

static constexpr int C_DIM   = 128;
static constexpr int THREADS = 256;
static constexpr int WARPS   = 8;
static constexpr int STAGE   = 96;                       // frames staged (48 KB)
static constexpr int KSTG    = STAGE / WARPS;            // 12
static constexpr int MAX_SEG = 4096;
static constexpr int SMEM_BYTES = (STAGE * C_DIM + WARPS * C_DIM + C_DIM) * 4; // 53,760

__device__ int g_seg[MAX_SEG + 1];

__global__ void seg_bounds_kernel(const int* __restrict__ idx, int Fn, int Bn)
{
    const int t = blockIdx.x * blockDim.x + threadIdx.x;
    if (t > Bn) return;
    int lo = 0, hi = Fn;
    while (lo < hi) {
        int m = (lo + hi) >> 1;
        if (idx[m] < t) lo = m + 1; else hi = m;
    }
    g_seg[t] = lo;
}

__device__ __forceinline__ float warp_gate(float d) {
#pragma unroll
    for (int s = 16; s > 0; s >>= 1)
        d += __shfl_xor_sync(0xffffffffu, d, s);
    return 1.f / (1.f + __expf(-d));
}

__global__ __launch_bounds__(THREADS, 4)
void gca_fused_kernel(const float* __restrict__ x,
                      const float* __restrict__ W,
                      float*       __restrict__ out,
                      int Jn, int Fn, int Bn)
{
    extern __shared__ float dyn[];
    float* s_buf = dyn;                        // STAGE x 128 staged head
    float* s_red = dyn + STAGE * C_DIM;        // 8 x 128
    float* s_vec = s_red + WARPS * C_DIM;      // 128: mean, then gc

    const int tid  = threadIdx.x;
    const int warp = tid >> 5;
    const int lane = tid & 31;
    const int b    = blockIdx.x;
    const int j    = blockIdx.y;

    const int start = g_seg[b];
    const int end   = g_seg[b + 1];
    const int cnt   = end - start;
    const float inv_cnt = 1.0f / (float)(cnt > 0 ? cnt : 1);
    const int ch = lane * 4;
    const float* xj = x + (size_t)j * Fn * C_DIM;

    // ---------------- pass 1a: staged head (load + STS + sum) ----------------
    float4 acc = make_float4(0.f, 0.f, 0.f, 0.f);
#pragma unroll
    for (int k = 0; k < KSTG; k++) {
        const int fl = warp + k * WARPS;       // 0..STAGE-1, uniform per k
        const int fr = start + fl;
        if (fr < end) {
            const float4 a = *(const float4*)(xj + (size_t)fr * C_DIM + ch);
            *(float4*)&s_buf[fl * C_DIM + ch] = a;
            acc.x += a.x; acc.y += a.y; acc.z += a.z; acc.w += a.w;
        }
    }
    // ---------------- pass 1b: remaining frames (pure stream, unroll 8) ------
    int f = start + STAGE + warp;
    for (; f + 7 * WARPS < end; f += 8 * WARPS) {
#pragma unroll
        for (int u = 0; u < 8; u++) {
            const float4 a = *(const float4*)(xj + (size_t)(f + u * WARPS) * C_DIM + ch);
            acc.x += a.x; acc.y += a.y; acc.z += a.z; acc.w += a.w;
        }
    }
    for (; f < end; f += WARPS) {
        const float4 a = *(const float4*)(xj + (size_t)f * C_DIM + ch);
        acc.x += a.x; acc.y += a.y; acc.z += a.z; acc.w += a.w;
    }
    *(float4*)&s_red[warp * C_DIM + ch] = acc;
    __syncthreads();
    if (tid < C_DIM) {
        float s = 0.f;
#pragma unroll
        for (int w = 0; w < WARPS; w++) s += s_red[w * C_DIM + tid];
        s_vec[tid] = s * inv_cnt;              // mean[j,b,:]
    }
    __syncthreads();

    // ---------------- GEMV: gc = tanh(mean @ W) ----------------
    {
        const int t_out = tid & (C_DIM - 1);
        const int half  = tid >> 7;            // 0..1
        const float* wp = W + (size_t)(half * 64) * C_DIM + t_out;
        float p = 0.f;
#pragma unroll 8
        for (int k = 0; k < 64; k++)
            p += s_vec[half * 64 + k] * wp[(size_t)k * C_DIM];
        s_red[half * C_DIM + t_out] = p;
    }
    __syncthreads();
    if (tid < C_DIM)
        s_vec[tid] = tanhf(s_red[tid] + s_red[C_DIM + tid]);
    __syncthreads();

    // ---------------- pass 2a: staged head from smem (unroll 4) --------------
    const float4 gc4 = *(const float4*)&s_vec[ch];
    float4 oacc = make_float4(0.f, 0.f, 0.f, 0.f);
    const int lim = cnt < STAGE ? cnt : STAGE;
    int fl = warp;
    for (; fl + 3 * WARPS < lim; fl += 4 * WARPS) {
        float4 a[4];
#pragma unroll
        for (int u = 0; u < 4; u++)
            a[u] = *(const float4*)&s_buf[(fl + u * WARPS) * C_DIM + ch];
        float d[4];
#pragma unroll
        for (int u = 0; u < 4; u++)
            d[u] = a[u].x*gc4.x + a[u].y*gc4.y + a[u].z*gc4.z + a[u].w*gc4.w;
#pragma unroll
        for (int s = 16; s > 0; s >>= 1) {
#pragma unroll
            for (int u = 0; u < 4; u++)
                d[u] += __shfl_xor_sync(0xffffffffu, d[u], s);
        }
#pragma unroll
        for (int u = 0; u < 4; u++) {
            const float g = 1.f / (1.f + __expf(-d[u]));
            oacc.x += g*a[u].x; oacc.y += g*a[u].y; oacc.z += g*a[u].z; oacc.w += g*a[u].w;
        }
    }
    for (; fl < lim; fl += WARPS) {
        const float4 a = *(const float4*)&s_buf[fl * C_DIM + ch];
        const float g = warp_gate(a.x*gc4.x + a.y*gc4.y + a.z*gc4.z + a.w*gc4.w);
        oacc.x += g*a.x; oacc.y += g*a.y; oacc.z += g*a.z; oacc.w += g*a.w;
    }

    // ---------------- pass 2b: tail from global (L2-resident, unroll 6) -------
    f = start + STAGE + warp;
    for (; f + 5 * WARPS < end; f += 6 * WARPS) {
        float4 a[6];
#pragma unroll
        for (int u = 0; u < 6; u++)
            a[u] = *(const float4*)(xj + (size_t)(f + u * WARPS) * C_DIM + ch);
        float d[6];
#pragma unroll
        for (int u = 0; u < 6; u++)
            d[u] = a[u].x*gc4.x + a[u].y*gc4.y + a[u].z*gc4.z + a[u].w*gc4.w;
#pragma unroll
        for (int s = 16; s > 0; s >>= 1) {
#pragma unroll
            for (int u = 0; u < 6; u++)
                d[u] += __shfl_xor_sync(0xffffffffu, d[u], s);
        }
#pragma unroll
        for (int u = 0; u < 6; u++) {
            const float g = 1.f / (1.f + __expf(-d[u]));
            oacc.x += g*a[u].x; oacc.y += g*a[u].y; oacc.z += g*a[u].z; oacc.w += g*a[u].w;
        }
    }
    for (; f < end; f += WARPS) {
        const float4 a = *(const float4*)(xj + (size_t)f * C_DIM + ch);
        const float g = warp_gate(a.x*gc4.x + a.y*gc4.y + a.z*gc4.z + a.w*gc4.w);
        oacc.x += g*a.x; oacc.y += g*a.y; oacc.z += g*a.z; oacc.w += g*a.w;
    }

    __syncthreads();
    *(float4*)&s_red[warp * C_DIM + ch] = oacc;
    __syncthreads();
    if (tid < C_DIM) {
        float s = 0.f;
#pragma unroll
        for (int w = 0; w < WARPS; w++) s += s_red[w * C_DIM + tid];
        out[((size_t)j * Bn + b) * C_DIM + tid] = s * inv_cnt;
    }
}

extern "C" void kernel_launch(void* const* d_in, const int* in_sizes, int n_in,
                              void* d_out, int out_size)
{
    // Identify inputs by element count: x = largest; weight = C*C; idx = other multi-element.
    int xi = 0;
    for (int i = 1; i < n_in; i++)
        if (in_sizes[i] > in_sizes[xi]) xi = i;
    int wi = -1, ii = -1;
    for (int i = 0; i < n_in; i++) {
        if (i == xi) continue;
        if (in_sizes[i] == C_DIM * C_DIM && wi < 0) { wi = i; continue; }
        if (in_sizes[i] > 1 && ii < 0) ii = i;
    }
    if (wi < 0 || ii < 0) return;

    const float* x   = (const float*)d_in[xi];
    const int*   idx = (const int*)  d_in[ii];
    const float* W   = (const float*)d_in[wi];
    float*       out = (float*)d_out;

    const int Fn = in_sizes[ii];
    const int Jn = in_sizes[xi] / (Fn * C_DIM);
    int Bn = out_size / (Jn * C_DIM);
    if (Bn > MAX_SEG) Bn = MAX_SEG;

    static bool attr_set = false;
    if (!attr_set) {
        cudaFuncSetAttribute(gca_fused_kernel,
                             cudaFuncAttributeMaxDynamicSharedMemorySize, SMEM_BYTES);
        attr_set = true;
    }

    seg_bounds_kernel<<<(Bn + 255) / 256 + 1, 256>>>(idx, Fn, Bn);
    dim3 grid(Bn, Jn);
    gca_fused_kernel<<<grid, THREADS, SMEM_BYTES>>>(x, W, out, Jn, Fn, Bn);
}